// round 4
// baseline (speedup 1.0000x reference)
#include <cuda_runtime.h>
#include <cuda_bf16.h>
#include <cstdint>
#include <cstddef>

// ---------------------------------------------------------------------------
// SageLayer fused pipeline v4: gather+GEMM fused into one kernel.
//   out[b] = normalize(leaky( X @ A^T + c ))[nodes_idx]
//   X[u] = [ emb[uid[u]] | mean_k emb[adj[u,k]] | mean_k emb[dis[u,k]] ]
//   A, c folded (exact algebra). GEMM: bf16 split hi*hi + hi*lo + lo*hi.
//   Per CTA: gather 128 rows -> smem X tile (bf16 hi/lo), then HMMA GEMM with
//   A from persistent smem and B streamed via 3-stage cp.async (1 sync/iter).
// ---------------------------------------------------------------------------

#define U_NODES 16384
#define K_NEIGH 32
#define D_IN    128
#define D_OUT   384
#define B_OUT   32768

// ---- device scratch ----
__device__ __align__(16) float g_Padj[128 * 128];
__device__ __align__(16) float g_Pdis[128 * 128];
__device__ __align__(16) float g_qadj[128];
__device__ __align__(16) float g_qdis[128];
__device__ __align__(16) float g_c[384];
__device__ __align__(16) __nv_bfloat16 g_Bhi[384 * 384];   // folded A[n][k]
__device__ __align__(16) __nv_bfloat16 g_Blo[384 * 384];
__device__ __align__(16) float g_Y[(size_t)U_NODES * 384];

// ---- smem layout of fused kernel (dynamic) ----
// Xhi: 128 rows x 392 bf16 (stride 392 elems = 784 B)  -> 100352 B
// Xlo: same                                            -> 100352 B
// B stages: 3 x (128 rows x 40 bf16, 80 B rows)        -> 30720 B
#define XSTRIDE   392
#define XROW_B    784
#define X_BYTES   (128 * XROW_B)          // 100352
#define BSTAGE_B  (128 * 80)              // 10240
#define SM_XHI    0
#define SM_XLO    X_BYTES
#define SM_B      (2 * X_BYTES)           // 200704
#define SM_TOTAL  (2 * X_BYTES + 3 * BSTAGE_B)   // 231424 <= 232448 opt-in

// ---- helpers ----
__device__ __forceinline__ uint32_t smem_u32(const void* p) {
    uint32_t a;
    asm("{ .reg .u64 t; cvta.to.shared.u64 t, %1; cvt.u32.u64 %0, t; }"
        : "=r"(a) : "l"(p));
    return a;
}
__device__ __forceinline__ void cp_async16(uint32_t dst, const void* src) {
    asm volatile("cp.async.cg.shared.global [%0], [%1], 16;"
                 :: "r"(dst), "l"(src) : "memory");
}
__device__ __forceinline__ void cp_commit() {
    asm volatile("cp.async.commit_group;" ::: "memory");
}
template <int N>
__device__ __forceinline__ void cp_wait() {
    asm volatile("cp.async.wait_group %0;" :: "n"(N) : "memory");
}
__device__ __forceinline__ void ldsm_x4(uint32_t& r0, uint32_t& r1,
                                        uint32_t& r2, uint32_t& r3, uint32_t a) {
    asm volatile("ldmatrix.sync.aligned.m8n8.x4.shared.b16 {%0,%1,%2,%3}, [%4];"
                 : "=r"(r0), "=r"(r1), "=r"(r2), "=r"(r3) : "r"(a));
}
__device__ __forceinline__ void mma16816(float& c0, float& c1, float& c2, float& c3,
                                         uint32_t a0, uint32_t a1, uint32_t a2, uint32_t a3,
                                         uint32_t b0, uint32_t b1) {
    asm volatile(
        "mma.sync.aligned.m16n8k16.row.col.f32.bf16.bf16.f32 "
        "{%0,%1,%2,%3}, {%4,%5,%6,%7}, {%8,%9}, {%0,%1,%2,%3};"
        : "+f"(c0), "+f"(c1), "+f"(c2), "+f"(c3)
        : "r"(a0), "r"(a1), "r"(a2), "r"(a3), "r"(b0), "r"(b1));
}
__device__ __forceinline__ void split_bf16(float x, __nv_bfloat16& h, __nv_bfloat16& l) {
    h = __float2bfloat16(x);
    l = __float2bfloat16(x - __bfloat162float(h));
}

// ---------------------------------------------------------------------------
// fold1: P = W @ Wa (128x128), q = W @ ba   for adj/dis
// ---------------------------------------------------------------------------
__global__ void fold1_kernel(const float* __restrict__ W_adj,
                             const float* __restrict__ Wa_adj,
                             const float* __restrict__ ba_adj,
                             const float* __restrict__ W_dis,
                             const float* __restrict__ Wa_dis,
                             const float* __restrict__ ba_dis) {
    const int g = blockIdx.x;
    const int which = blockIdx.y;
    const int d = threadIdx.x;

    const float* W  = which ? W_dis  : W_adj;
    const float* Wa = which ? Wa_dis : Wa_adj;
    const float* ba = which ? ba_dis : ba_adj;
    float* P = which ? g_Pdis : g_Padj;
    float* q = which ? g_qdis : g_qadj;

    float acc = 0.f;
#pragma unroll 8
    for (int e = 0; e < 128; e++)
        acc += W[g * 128 + e] * Wa[e * 128 + d];
    P[g * 128 + d] = acc;

    __shared__ float red[128];
    red[d] = W[g * 128 + d] * ba[d];
    __syncthreads();
#pragma unroll
    for (int s = 64; s > 0; s >>= 1) {
        if (d < s) red[d] += red[d + s];
        __syncthreads();
    }
    if (d == 0) q[g] = red[0];
}

// ---------------------------------------------------------------------------
// fold2: folded A[n][k] -> bf16 hi/lo (row-major N x K), and c[n]
// ---------------------------------------------------------------------------
__global__ void fold2_kernel(const float* __restrict__ WC,
                             const float* __restrict__ W_self,
                             const float* __restrict__ bWC,
                             const float* __restrict__ bias) {
    const int n = blockIdx.x;
    const int k = threadIdx.x;

    float acc = 0.f;
    if (k < 128) {
#pragma unroll 8
        for (int e = 0; e < 128; e++)
            acc += WC[n * 384 + e] * W_self[e * 128 + k];
    } else if (k < 256) {
        const int kk = k - 128;
#pragma unroll 8
        for (int g = 0; g < 128; g++)
            acc += WC[n * 384 + 128 + g] * g_Padj[g * 128 + kk];
    } else {
        const int kk = k - 256;
#pragma unroll 8
        for (int g = 0; g < 128; g++)
            acc += WC[n * 384 + 256 + g] * g_Pdis[g * 128 + kk];
    }
    __nv_bfloat16 h, l;
    split_bf16(acc, h, l);
    g_Bhi[n * 384 + k] = h;
    g_Blo[n * 384 + k] = l;

    float cp = 0.f;
    if (k >= 128 && k < 256) cp = WC[n * 384 + k] * g_qadj[k - 128];
    else if (k >= 256)       cp = WC[n * 384 + k] * g_qdis[k - 256];

    __shared__ float red[384];
    red[k] = cp;
    __syncthreads();
    if (k < 128) red[k] = red[k] + red[k + 128] + red[k + 256];
    __syncthreads();
#pragma unroll
    for (int s = 64; s > 0; s >>= 1) {
        if (k < s) red[k] += red[k + s];
        __syncthreads();
    }
    if (k == 0) g_c[n] = red[0] + bWC[n] + bias[n];
}

// ---------------------------------------------------------------------------
// fused gather + GEMM
// grid = 128 CTAs (one 128-row M tile each), 256 threads, 231 KB dynamic smem
// ---------------------------------------------------------------------------
__global__ __launch_bounds__(256, 1) void fused_kernel(
        const float* __restrict__ emb,
        const int* __restrict__ uid,
        const int* __restrict__ adj,
        const int* __restrict__ dis) {
    extern __shared__ char smem[];
    __nv_bfloat16* Xhi = (__nv_bfloat16*)(smem + SM_XHI);
    __nv_bfloat16* Xlo = (__nv_bfloat16*)(smem + SM_XLO);
    const uint32_t xhi_u = smem_u32(smem) + SM_XHI;
    const uint32_t xlo_u = smem_u32(smem) + SM_XLO;
    const uint32_t bs_u  = smem_u32(smem) + SM_B;

    const int t = threadIdx.x;
    const int m0 = blockIdx.x * 128;

    // ---------------- Phase 1: gather + mean + split into smem X tile -------
    {
        const int half = t >> 7;      // 0/1
        const int d = t & 127;        // dim
        for (int i = 0; i < 64; i++) {
            const int row = i * 2 + half;
            const int u = m0 + row;
            const int* ap = adj + (size_t)u * K_NEIGH;
            const int* dp = dis + (size_t)u * K_NEIGH;
            float acc_a = 0.f, acc_d = 0.f;
#pragma unroll
            for (int k = 0; k < K_NEIGH; k++) {
                acc_a += emb[(size_t)ap[k] * D_IN + d];
                acc_d += emb[(size_t)dp[k] * D_IN + d];
            }
            const float selfv = emb[(size_t)uid[u] * D_IN + d];
            acc_a *= (1.0f / 32.0f);
            acc_d *= (1.0f / 32.0f);

            __nv_bfloat16 h, l;
            split_bf16(selfv, h, l);
            Xhi[row * XSTRIDE + d] = h;        Xlo[row * XSTRIDE + d] = l;
            split_bf16(acc_a, h, l);
            Xhi[row * XSTRIDE + 128 + d] = h;  Xlo[row * XSTRIDE + 128 + d] = l;
            split_bf16(acc_d, h, l);
            Xhi[row * XSTRIDE + 256 + d] = h;  Xlo[row * XSTRIDE + 256 + d] = l;
        }
    }
    __syncthreads();

    // ---------------- Phase 2: GEMM over 3 N-tiles --------------------------
    const int lane = t & 31;
    const int wid = t >> 5;
    const int wm = wid & 3;          // 4 m-warps x 32 rows
    const int wn = wid >> 2;         // 2 n-warps x 64 cols
    const uint32_t a_lm = (uint32_t)((lane & 15) * XROW_B + (lane >> 4) * 16);
    const uint32_t b_lm = (uint32_t)(((lane & 7) + ((lane >> 4) << 3)) * 80
                                     + (((lane >> 3) & 1) << 4));

    // B chunk load for virtual iter it (0..35) into stage s
    auto loadB = [&](int it, int s, int n0) {
        const int p = it / 12;
        const int kc = (it % 12) * 32;
        const __nv_bfloat16* Bsrc = (p == 1) ? g_Blo : g_Bhi;
#pragma unroll
        for (int j = 0; j < 2; j++) {
            const int c = t + j * 256;           // 0..511
            const int rr = c >> 2;               // B row 0..127
            const int ch = c & 3;                // 16B chunk
            cp_async16(bs_u + (uint32_t)(s * BSTAGE_B + rr * 80 + ch * 16),
                       Bsrc + (size_t)(n0 + rr) * 384 + kc + ch * 8);
        }
        cp_commit();
    };

    for (int nt = 0; nt < 3; nt++) {
        const int n0 = nt * 128;

        float acc[2][8][4];
#pragma unroll
        for (int i = 0; i < 2; i++)
#pragma unroll
            for (int j = 0; j < 8; j++)
#pragma unroll
                for (int q = 0; q < 4; q++) acc[i][j][q] = 0.f;

        loadB(0, 0, n0);
        loadB(1, 1, n0);

        for (int it = 0; it < 36; it++) {
            if (it == 35) cp_wait<0>(); else cp_wait<1>();
            __syncthreads();

            const int p = it / 12;
            const int kc = (it % 12) * 32;
            const uint32_t xbase = (p < 2) ? xhi_u : xlo_u;
            const uint32_t a_tile = xbase + (uint32_t)(wm * 32 * XROW_B + kc * 2) + a_lm;
            const uint32_t b_tile = bs_u + (uint32_t)((it % 3) * BSTAGE_B + wn * 64 * 80) + b_lm;

#pragma unroll
            for (int ks = 0; ks < 2; ks++) {
                uint32_t af[2][4];
                uint32_t bf_[4][4];
#pragma unroll
                for (int mi = 0; mi < 2; mi++)
                    ldsm_x4(af[mi][0], af[mi][1], af[mi][2], af[mi][3],
                            a_tile + (uint32_t)(mi * 16 * XROW_B + ks * 32));
#pragma unroll
                for (int bj = 0; bj < 4; bj++)
                    ldsm_x4(bf_[bj][0], bf_[bj][1], bf_[bj][2], bf_[bj][3],
                            b_tile + (uint32_t)(bj * 16 * 80 + ks * 32));
#pragma unroll
                for (int mi = 0; mi < 2; mi++)
#pragma unroll
                    for (int nj = 0; nj < 8; nj++)
                        mma16816(acc[mi][nj][0], acc[mi][nj][1],
                                 acc[mi][nj][2], acc[mi][nj][3],
                                 af[mi][0], af[mi][1], af[mi][2], af[mi][3],
                                 bf_[nj >> 1][(nj & 1) * 2],
                                 bf_[nj >> 1][(nj & 1) * 2 + 1]);
            }

            if (it + 2 < 36) loadB(it + 2, (it + 2) % 3, n0);
        }
        __syncthreads();   // all compute done before next N-tile reuses stages

        // epilogue: += c, leaky relu, store to g_Y
        float cv[8][2];
#pragma unroll
        for (int nj = 0; nj < 8; nj++) {
            const int col = n0 + wn * 64 + nj * 8 + (lane & 3) * 2;
            cv[nj][0] = g_c[col];
            cv[nj][1] = g_c[col + 1];
        }
#pragma unroll
        for (int mi = 0; mi < 2; mi++) {
            const int row = m0 + wm * 32 + mi * 16 + (lane >> 2);
#pragma unroll
            for (int nj = 0; nj < 8; nj++) {
                const int col = n0 + wn * 64 + nj * 8 + (lane & 3) * 2;
                float y0 = acc[mi][nj][0] + cv[nj][0];
                float y1 = acc[mi][nj][1] + cv[nj][1];
                float y2 = acc[mi][nj][2] + cv[nj][0];
                float y3 = acc[mi][nj][3] + cv[nj][1];
                y0 = (y0 > 0.f) ? y0 : 0.2f * y0;
                y1 = (y1 > 0.f) ? y1 : 0.2f * y1;
                y2 = (y2 > 0.f) ? y2 : 0.2f * y2;
                y3 = (y3 > 0.f) ? y3 : 0.2f * y3;
                *(float2*)&g_Y[(size_t)row * 384 + col]       = make_float2(y0, y1);
                *(float2*)&g_Y[(size_t)(row + 8) * 384 + col] = make_float2(y2, y3);
            }
        }
    }
}

// ---------------------------------------------------------------------------
// norm_gather: out[b] = normalize(Y[nodes_idx[b]])
// ---------------------------------------------------------------------------
__global__ void norm_gather_kernel(const int* __restrict__ nodes_idx,
                                   float* __restrict__ out) {
    const int w = threadIdx.x >> 5;
    const int l = threadIdx.x & 31;
    const int b = blockIdx.x * 8 + w;
    const int u = nodes_idx[b];

    const float4* yr = (const float4*)(g_Y + (size_t)u * 384);
    float4 v0 = yr[l];
    float4 v1 = yr[l + 32];
    float4 v2 = yr[l + 64];

    float s = v0.x * v0.x + v0.y * v0.y + v0.z * v0.z + v0.w * v0.w
            + v1.x * v1.x + v1.y * v1.y + v1.z * v1.z + v1.w * v1.w
            + v2.x * v2.x + v2.y * v2.y + v2.z * v2.z + v2.w * v2.w;
#pragma unroll
    for (int off = 16; off > 0; off >>= 1)
        s += __shfl_xor_sync(0xffffffffu, s, off);

    const float inv = 1.0f / fmaxf(sqrtf(s), 1e-12f);

    float4* o = (float4*)(out + (size_t)b * 384);
    v0.x *= inv; v0.y *= inv; v0.z *= inv; v0.w *= inv;
    v1.x *= inv; v1.y *= inv; v1.z *= inv; v1.w *= inv;
    v2.x *= inv; v2.y *= inv; v2.z *= inv; v2.w *= inv;
    o[l]      = v0;
    o[l + 32] = v1;
    o[l + 64] = v2;
}

// ---------------------------------------------------------------------------
extern "C" void kernel_launch(void* const* d_in, const int* in_sizes, int n_in,
                              void* d_out, int out_size) {
    const float* emb    = (const float*)d_in[0];
    const float* Wa_adj = (const float*)d_in[1];
    const float* ba_adj = (const float*)d_in[2];
    const float* Wa_dis = (const float*)d_in[3];
    const float* ba_dis = (const float*)d_in[4];
    const float* W_self = (const float*)d_in[5];
    const float* W_adj  = (const float*)d_in[6];
    const float* W_dis  = (const float*)d_in[7];
    const float* WC     = (const float*)d_in[8];
    const float* bWC    = (const float*)d_in[9];
    const float* bias   = (const float*)d_in[10];
    const int* uid      = (const int*)d_in[11];
    const int* adj      = (const int*)d_in[12];
    const int* dis      = (const int*)d_in[13];
    const int* nidx     = (const int*)d_in[14];
    float* out          = (float*)d_out;

    cudaFuncSetAttribute(fused_kernel,
                         cudaFuncAttributeMaxDynamicSharedMemorySize, SM_TOTAL);

    fold1_kernel<<<dim3(128, 2), 128>>>(W_adj, Wa_adj, ba_adj,
                                        W_dis, Wa_dis, ba_dis);
    fold2_kernel<<<384, 384>>>(WC, W_self, bWC, bias);
    fused_kernel<<<128, 256, SM_TOTAL>>>(emb, uid, adj, dis);
    norm_gather_kernel<<<B_OUT / 8, 256>>>(nidx, out);
}

// round 5
// speedup vs baseline: 1.3554x; 1.3554x over previous
#include <cuda_runtime.h>
#include <cuda_bf16.h>
#include <cstdint>
#include <cstddef>

// ---------------------------------------------------------------------------
// SageLayer pipeline v5 (split structure of R3 + deeper GEMM pipeline)
//   out[b] = normalize(leaky( X @ A^T + c ))[nodes_idx]
//   X[u] = [ emb[uid[u]] | mean_k emb[adj[u,k]] | mean_k emb[dis[u,k]] ]
//   A, c folded (exact algebra). GEMM: bf16 split hi*hi + hi*lo + lo*hi,
//   virtual K = 1152, k-chunk 64, 3-stage cp.async, 1 sync/iter, 18 iters.
// ---------------------------------------------------------------------------

#define U_NODES 16384
#define K_NEIGH 32
#define D_IN    128
#define D_OUT   384
#define B_OUT   32768

// ---- device scratch ----
__device__ __align__(16) float g_Padj[128 * 128];
__device__ __align__(16) float g_Pdis[128 * 128];
__device__ __align__(16) float g_qadj[128];
__device__ __align__(16) float g_qdis[128];
__device__ __align__(16) float g_c[384];
__device__ __align__(16) __nv_bfloat16 g_Xhi[(size_t)U_NODES * 384];
__device__ __align__(16) __nv_bfloat16 g_Xlo[(size_t)U_NODES * 384];
__device__ __align__(16) __nv_bfloat16 g_Bhi[384 * 384];   // folded A[n][k]
__device__ __align__(16) __nv_bfloat16 g_Blo[384 * 384];
__device__ __align__(16) float g_Y[(size_t)U_NODES * 384];

// ---- helpers ----
__device__ __forceinline__ uint32_t smem_u32(const void* p) {
    uint32_t a;
    asm("{ .reg .u64 t; cvta.to.shared.u64 t, %1; cvt.u32.u64 %0, t; }"
        : "=r"(a) : "l"(p));
    return a;
}
__device__ __forceinline__ void cp_async16(uint32_t dst, const void* src) {
    asm volatile("cp.async.cg.shared.global [%0], [%1], 16;"
                 :: "r"(dst), "l"(src) : "memory");
}
__device__ __forceinline__ void cp_commit() {
    asm volatile("cp.async.commit_group;" ::: "memory");
}
template <int N>
__device__ __forceinline__ void cp_wait() {
    asm volatile("cp.async.wait_group %0;" :: "n"(N) : "memory");
}
__device__ __forceinline__ void ldsm_x4(uint32_t& r0, uint32_t& r1,
                                        uint32_t& r2, uint32_t& r3, uint32_t a) {
    asm volatile("ldmatrix.sync.aligned.m8n8.x4.shared.b16 {%0,%1,%2,%3}, [%4];"
                 : "=r"(r0), "=r"(r1), "=r"(r2), "=r"(r3) : "r"(a));
}
__device__ __forceinline__ void mma16816(float& c0, float& c1, float& c2, float& c3,
                                         uint32_t a0, uint32_t a1, uint32_t a2, uint32_t a3,
                                         uint32_t b0, uint32_t b1) {
    asm volatile(
        "mma.sync.aligned.m16n8k16.row.col.f32.bf16.bf16.f32 "
        "{%0,%1,%2,%3}, {%4,%5,%6,%7}, {%8,%9}, {%0,%1,%2,%3};"
        : "+f"(c0), "+f"(c1), "+f"(c2), "+f"(c3)
        : "r"(a0), "r"(a1), "r"(a2), "r"(a3), "r"(b0), "r"(b1));
}
__device__ __forceinline__ void split_bf16(float x, __nv_bfloat16& h, __nv_bfloat16& l) {
    h = __float2bfloat16(x);
    l = __float2bfloat16(x - __bfloat162float(h));
}

// ---------------------------------------------------------------------------
// fold1: P = W @ Wa (128x128), q = W @ ba   for adj/dis
// ---------------------------------------------------------------------------
__global__ void fold1_kernel(const float* __restrict__ W_adj,
                             const float* __restrict__ Wa_adj,
                             const float* __restrict__ ba_adj,
                             const float* __restrict__ W_dis,
                             const float* __restrict__ Wa_dis,
                             const float* __restrict__ ba_dis) {
    const int g = blockIdx.x;
    const int which = blockIdx.y;
    const int d = threadIdx.x;

    const float* W  = which ? W_dis  : W_adj;
    const float* Wa = which ? Wa_dis : Wa_adj;
    const float* ba = which ? ba_dis : ba_adj;
    float* P = which ? g_Pdis : g_Padj;
    float* q = which ? g_qdis : g_qadj;

    float acc = 0.f;
#pragma unroll 8
    for (int e = 0; e < 128; e++)
        acc += W[g * 128 + e] * Wa[e * 128 + d];
    P[g * 128 + d] = acc;

    __shared__ float red[128];
    red[d] = W[g * 128 + d] * ba[d];
    __syncthreads();
#pragma unroll
    for (int s = 64; s > 0; s >>= 1) {
        if (d < s) red[d] += red[d + s];
        __syncthreads();
    }
    if (d == 0) q[g] = red[0];
}

// ---------------------------------------------------------------------------
// fold2: folded A[n][k] -> bf16 hi/lo (row-major N x K), and c[n]
// ---------------------------------------------------------------------------
__global__ void fold2_kernel(const float* __restrict__ WC,
                             const float* __restrict__ W_self,
                             const float* __restrict__ bWC,
                             const float* __restrict__ bias) {
    const int n = blockIdx.x;
    const int k = threadIdx.x;

    float acc = 0.f;
    if (k < 128) {
#pragma unroll 8
        for (int e = 0; e < 128; e++)
            acc += WC[n * 384 + e] * W_self[e * 128 + k];
    } else if (k < 256) {
        const int kk = k - 128;
#pragma unroll 8
        for (int g = 0; g < 128; g++)
            acc += WC[n * 384 + 128 + g] * g_Padj[g * 128 + kk];
    } else {
        const int kk = k - 256;
#pragma unroll 8
        for (int g = 0; g < 128; g++)
            acc += WC[n * 384 + 256 + g] * g_Pdis[g * 128 + kk];
    }
    __nv_bfloat16 h, l;
    split_bf16(acc, h, l);
    g_Bhi[n * 384 + k] = h;
    g_Blo[n * 384 + k] = l;

    float cp = 0.f;
    if (k >= 128 && k < 256) cp = WC[n * 384 + k] * g_qadj[k - 128];
    else if (k >= 256)       cp = WC[n * 384 + k] * g_qdis[k - 256];

    __shared__ float red[384];
    red[k] = cp;
    __syncthreads();
    if (k < 128) red[k] = red[k] + red[k + 128] + red[k + 256];
    __syncthreads();
#pragma unroll
    for (int s = 64; s > 0; s >>= 1) {
        if (k < s) red[k] += red[k + s];
        __syncthreads();
    }
    if (k == 0) g_c[n] = red[0] + bWC[n] + bias[n];
}

// ---------------------------------------------------------------------------
// gather_mean: X[u] = [self | mean_adj | mean_dis] -> bf16 hi/lo
// 16384 CTAs x 128 threads: max outstanding-load parallelism (DRAM-bound).
// ---------------------------------------------------------------------------
__global__ void gather_mean_kernel(const float* __restrict__ emb,
                                   const int* __restrict__ uid,
                                   const int* __restrict__ adj,
                                   const int* __restrict__ dis) {
    const int u = blockIdx.x;
    const int t = threadIdx.x;

    __shared__ int sa[K_NEIGH];
    __shared__ int sd[K_NEIGH];
    __shared__ int sself;
    if (t < 32)       sa[t]      = adj[u * K_NEIGH + t];
    else if (t < 64)  sd[t - 32] = dis[u * K_NEIGH + (t - 32)];
    else if (t == 64) sself      = uid[u];
    __syncthreads();

    float acc_a = 0.f, acc_d = 0.f;
#pragma unroll
    for (int k = 0; k < K_NEIGH; k++) {
        acc_a += emb[(size_t)sa[k] * D_IN + t];
        acc_d += emb[(size_t)sd[k] * D_IN + t];
    }
    const float selfv = emb[(size_t)sself * D_IN + t];
    acc_a *= (1.0f / 32.0f);
    acc_d *= (1.0f / 32.0f);

    const size_t r = (size_t)u * 384;
    __nv_bfloat16 h, l;
    split_bf16(selfv, h, l);  g_Xhi[r + t] = h;        g_Xlo[r + t] = l;
    split_bf16(acc_a, h, l);  g_Xhi[r + 128 + t] = h;  g_Xlo[r + 128 + t] = l;
    split_bf16(acc_d, h, l);  g_Xhi[r + 256 + t] = h;  g_Xlo[r + 256 + t] = l;
}

// ---------------------------------------------------------------------------
// GEMM: Y = leaky( X[16384,384] @ A^T + c ) via mma.sync bf16x3
// Virtual K' = 1152. CTA 128x128, 8 warps (4m x 2n), warp tile 32x64.
// k-chunk 64, 3-stage cp.async pipeline, ONE __syncthreads per iter, 18 iters.
// smem rows padded to 144 B (stride 36 words -> conflict-free ldmatrix).
// ---------------------------------------------------------------------------
#define KCH      64
#define ROWB     144                    // bytes per smem row (64 bf16 + pad)
#define STG_OP   (128 * ROWB)           // 18432 B per operand per stage
#define STG_B    (2 * STG_OP)           // 36864 B per stage (A+B)
#define NSTG     3
#define GSM_TOT  (NSTG * STG_B)         // 110592 B

__global__ __launch_bounds__(256, 2) void gemm_hmma_kernel() {
    extern __shared__ char gsm[];
    const uint32_t base = smem_u32(gsm);

    const int t = threadIdx.x;
    const int lane = t & 31;
    const int wid = t >> 5;
    const int wm = wid & 3;          // 4 m-warps x 32 rows
    const int wn = wid >> 2;         // 2 n-warps x 64 cols
    const int n0 = blockIdx.x * 128;
    const int m0 = blockIdx.y * 128;

    // ldmatrix per-lane address offsets (bytes)
    const uint32_t a_lm = (uint32_t)((lane & 15) * ROWB + (lane >> 4) * 16);
    const uint32_t b_lm = (uint32_t)(((lane & 7) + ((lane >> 4) << 3)) * ROWB
                                     + (((lane >> 3) & 1) << 4));

    float acc[2][8][4];
#pragma unroll
    for (int i = 0; i < 2; i++)
#pragma unroll
        for (int j = 0; j < 8; j++)
#pragma unroll
            for (int q = 0; q < 4; q++) acc[i][j][q] = 0.f;

    // load k-chunk for virtual iter it (0..17) into stage s
    auto load_iter = [&](int it, int s) {
        const int p  = it / 6;                 // product index 0,1,2
        const int kc = (it % 6) * KCH;         // k offset within 384
        const __nv_bfloat16* Asrc = (p < 2) ? g_Xhi : g_Xlo;
        const __nv_bfloat16* Bsrc = (p == 1) ? g_Blo : g_Bhi;
        const uint32_t sb = base + (uint32_t)(s * STG_B);
#pragma unroll
        for (int j = 0; j < 4; j++) {
            const int q = t + j * 256;          // 0..1023
            const int r = q >> 3;               // row 0..127
            const int ch = q & 7;               // 16B chunk (8 per 128B row)
            cp_async16(sb + (uint32_t)(r * ROWB + ch * 16),
                       Asrc + (size_t)(m0 + r) * 384 + kc + ch * 8);
            cp_async16(sb + (uint32_t)(STG_OP + r * ROWB + ch * 16),
                       Bsrc + (size_t)(n0 + r) * 384 + kc + ch * 8);
        }
        cp_commit();
    };

    load_iter(0, 0);
    load_iter(1, 1);

    for (int it = 0; it < 18; it++) {
        if (it == 17) cp_wait<0>(); else cp_wait<1>();
        __syncthreads();

        const int s = it % NSTG;
        const uint32_t a_tile = base + (uint32_t)(s * STG_B + wm * 32 * ROWB) + a_lm;
        const uint32_t b_tile = base + (uint32_t)(s * STG_B + STG_OP + wn * 64 * ROWB) + b_lm;

#pragma unroll
        for (int ks = 0; ks < 4; ks++) {
            uint32_t af[2][4];
            uint32_t bf_[4][4];
#pragma unroll
            for (int mi = 0; mi < 2; mi++)
                ldsm_x4(af[mi][0], af[mi][1], af[mi][2], af[mi][3],
                        a_tile + (uint32_t)(mi * 16 * ROWB + ks * 32));
#pragma unroll
            for (int bj = 0; bj < 4; bj++)
                ldsm_x4(bf_[bj][0], bf_[bj][1], bf_[bj][2], bf_[bj][3],
                        b_tile + (uint32_t)(bj * 16 * ROWB + ks * 32));
#pragma unroll
            for (int mi = 0; mi < 2; mi++)
#pragma unroll
                for (int nj = 0; nj < 8; nj++)
                    mma16816(acc[mi][nj][0], acc[mi][nj][1],
                             acc[mi][nj][2], acc[mi][nj][3],
                             af[mi][0], af[mi][1], af[mi][2], af[mi][3],
                             bf_[nj >> 1][(nj & 1) * 2],
                             bf_[nj >> 1][(nj & 1) * 2 + 1]);
        }

        if (it + 2 < 18) load_iter(it + 2, (it + 2) % NSTG);
    }

    // ---- epilogue: += c, leaky relu, store to g_Y ----
    float cv[8][2];
#pragma unroll
    for (int nj = 0; nj < 8; nj++) {
        const int col = n0 + wn * 64 + nj * 8 + (lane & 3) * 2;
        cv[nj][0] = g_c[col];
        cv[nj][1] = g_c[col + 1];
    }
#pragma unroll
    for (int mi = 0; mi < 2; mi++) {
        const int row = m0 + wm * 32 + mi * 16 + (lane >> 2);
#pragma unroll
        for (int nj = 0; nj < 8; nj++) {
            const int col = n0 + wn * 64 + nj * 8 + (lane & 3) * 2;
            float y0 = acc[mi][nj][0] + cv[nj][0];
            float y1 = acc[mi][nj][1] + cv[nj][1];
            float y2 = acc[mi][nj][2] + cv[nj][0];
            float y3 = acc[mi][nj][3] + cv[nj][1];
            y0 = (y0 > 0.f) ? y0 : 0.2f * y0;
            y1 = (y1 > 0.f) ? y1 : 0.2f * y1;
            y2 = (y2 > 0.f) ? y2 : 0.2f * y2;
            y3 = (y3 > 0.f) ? y3 : 0.2f * y3;
            *(float2*)&g_Y[(size_t)row * 384 + col]       = make_float2(y0, y1);
            *(float2*)&g_Y[(size_t)(row + 8) * 384 + col] = make_float2(y2, y3);
        }
    }
}

// ---------------------------------------------------------------------------
// norm_gather: out[b] = normalize(Y[nodes_idx[b]])
// ---------------------------------------------------------------------------
__global__ void norm_gather_kernel(const int* __restrict__ nodes_idx,
                                   float* __restrict__ out) {
    const int w = threadIdx.x >> 5;
    const int l = threadIdx.x & 31;
    const int b = blockIdx.x * 8 + w;
    const int u = nodes_idx[b];

    const float4* yr = (const float4*)(g_Y + (size_t)u * 384);
    float4 v0 = yr[l];
    float4 v1 = yr[l + 32];
    float4 v2 = yr[l + 64];

    float s = v0.x * v0.x + v0.y * v0.y + v0.z * v0.z + v0.w * v0.w
            + v1.x * v1.x + v1.y * v1.y + v1.z * v1.z + v1.w * v1.w
            + v2.x * v2.x + v2.y * v2.y + v2.z * v2.z + v2.w * v2.w;
#pragma unroll
    for (int off = 16; off > 0; off >>= 1)
        s += __shfl_xor_sync(0xffffffffu, s, off);

    const float inv = 1.0f / fmaxf(sqrtf(s), 1e-12f);

    float4* o = (float4*)(out + (size_t)b * 384);
    v0.x *= inv; v0.y *= inv; v0.z *= inv; v0.w *= inv;
    v1.x *= inv; v1.y *= inv; v1.z *= inv; v1.w *= inv;
    v2.x *= inv; v2.y *= inv; v2.z *= inv; v2.w *= inv;
    o[l]      = v0;
    o[l + 32] = v1;
    o[l + 64] = v2;
}

// ---------------------------------------------------------------------------
extern "C" void kernel_launch(void* const* d_in, const int* in_sizes, int n_in,
                              void* d_out, int out_size) {
    const float* emb    = (const float*)d_in[0];
    const float* Wa_adj = (const float*)d_in[1];
    const float* ba_adj = (const float*)d_in[2];
    const float* Wa_dis = (const float*)d_in[3];
    const float* ba_dis = (const float*)d_in[4];
    const float* W_self = (const float*)d_in[5];
    const float* W_adj  = (const float*)d_in[6];
    const float* W_dis  = (const float*)d_in[7];
    const float* WC     = (const float*)d_in[8];
    const float* bWC    = (const float*)d_in[9];
    const float* bias   = (const float*)d_in[10];
    const int* uid      = (const int*)d_in[11];
    const int* adj      = (const int*)d_in[12];
    const int* dis      = (const int*)d_in[13];
    const int* nidx     = (const int*)d_in[14];
    float* out          = (float*)d_out;

    cudaFuncSetAttribute(gemm_hmma_kernel,
                         cudaFuncAttributeMaxDynamicSharedMemorySize, GSM_TOT);

    fold1_kernel<<<dim3(128, 2), 128>>>(W_adj, Wa_adj, ba_adj,
                                        W_dis, Wa_dis, ba_dis);
    fold2_kernel<<<384, 384>>>(WC, W_self, bWC, bias);
    gather_mean_kernel<<<U_NODES, 128>>>(emb, uid, adj, dis);
    gemm_hmma_kernel<<<dim3(3, 128), 256, GSM_TOT>>>();
    norm_gather_kernel<<<B_OUT / 8, 256>>>(nidx, out);
}

// round 6
// speedup vs baseline: 1.3556x; 1.0002x over previous
#include <cuda_runtime.h>
#include <cuda_bf16.h>
#include <cstdint>
#include <cstddef>

// ---------------------------------------------------------------------------
// SageLayer pipeline v5 (split structure of R3 + deeper GEMM pipeline)
//   out[b] = normalize(leaky( X @ A^T + c ))[nodes_idx]
//   X[u] = [ emb[uid[u]] | mean_k emb[adj[u,k]] | mean_k emb[dis[u,k]] ]
//   A, c folded (exact algebra). GEMM: bf16 split hi*hi + hi*lo + lo*hi,
//   virtual K = 1152, k-chunk 64, 3-stage cp.async, 1 sync/iter, 18 iters.
// ---------------------------------------------------------------------------

#define U_NODES 16384
#define K_NEIGH 32
#define D_IN    128
#define D_OUT   384
#define B_OUT   32768

// ---- device scratch ----
__device__ __align__(16) float g_Padj[128 * 128];
__device__ __align__(16) float g_Pdis[128 * 128];
__device__ __align__(16) float g_qadj[128];
__device__ __align__(16) float g_qdis[128];
__device__ __align__(16) float g_c[384];
__device__ __align__(16) __nv_bfloat16 g_Xhi[(size_t)U_NODES * 384];
__device__ __align__(16) __nv_bfloat16 g_Xlo[(size_t)U_NODES * 384];
__device__ __align__(16) __nv_bfloat16 g_Bhi[384 * 384];   // folded A[n][k]
__device__ __align__(16) __nv_bfloat16 g_Blo[384 * 384];
__device__ __align__(16) float g_Y[(size_t)U_NODES * 384];

// ---- helpers ----
__device__ __forceinline__ uint32_t smem_u32(const void* p) {
    uint32_t a;
    asm("{ .reg .u64 t; cvta.to.shared.u64 t, %1; cvt.u32.u64 %0, t; }"
        : "=r"(a) : "l"(p));
    return a;
}
__device__ __forceinline__ void cp_async16(uint32_t dst, const void* src) {
    asm volatile("cp.async.cg.shared.global [%0], [%1], 16;"
                 :: "r"(dst), "l"(src) : "memory");
}
__device__ __forceinline__ void cp_commit() {
    asm volatile("cp.async.commit_group;" ::: "memory");
}
template <int N>
__device__ __forceinline__ void cp_wait() {
    asm volatile("cp.async.wait_group %0;" :: "n"(N) : "memory");
}
__device__ __forceinline__ void ldsm_x4(uint32_t& r0, uint32_t& r1,
                                        uint32_t& r2, uint32_t& r3, uint32_t a) {
    asm volatile("ldmatrix.sync.aligned.m8n8.x4.shared.b16 {%0,%1,%2,%3}, [%4];"
                 : "=r"(r0), "=r"(r1), "=r"(r2), "=r"(r3) : "r"(a));
}
__device__ __forceinline__ void mma16816(float& c0, float& c1, float& c2, float& c3,
                                         uint32_t a0, uint32_t a1, uint32_t a2, uint32_t a3,
                                         uint32_t b0, uint32_t b1) {
    asm volatile(
        "mma.sync.aligned.m16n8k16.row.col.f32.bf16.bf16.f32 "
        "{%0,%1,%2,%3}, {%4,%5,%6,%7}, {%8,%9}, {%0,%1,%2,%3};"
        : "+f"(c0), "+f"(c1), "+f"(c2), "+f"(c3)
        : "r"(a0), "r"(a1), "r"(a2), "r"(a3), "r"(b0), "r"(b1));
}
__device__ __forceinline__ void split_bf16(float x, __nv_bfloat16& h, __nv_bfloat16& l) {
    h = __float2bfloat16(x);
    l = __float2bfloat16(x - __bfloat162float(h));
}

// ---------------------------------------------------------------------------
// fold1: P = W @ Wa (128x128), q = W @ ba   for adj/dis
// ---------------------------------------------------------------------------
__global__ void fold1_kernel(const float* __restrict__ W_adj,
                             const float* __restrict__ Wa_adj,
                             const float* __restrict__ ba_adj,
                             const float* __restrict__ W_dis,
                             const float* __restrict__ Wa_dis,
                             const float* __restrict__ ba_dis) {
    const int g = blockIdx.x;
    const int which = blockIdx.y;
    const int d = threadIdx.x;

    const float* W  = which ? W_dis  : W_adj;
    const float* Wa = which ? Wa_dis : Wa_adj;
    const float* ba = which ? ba_dis : ba_adj;
    float* P = which ? g_Pdis : g_Padj;
    float* q = which ? g_qdis : g_qadj;

    float acc = 0.f;
#pragma unroll 8
    for (int e = 0; e < 128; e++)
        acc += W[g * 128 + e] * Wa[e * 128 + d];
    P[g * 128 + d] = acc;

    __shared__ float red[128];
    red[d] = W[g * 128 + d] * ba[d];
    __syncthreads();
#pragma unroll
    for (int s = 64; s > 0; s >>= 1) {
        if (d < s) red[d] += red[d + s];
        __syncthreads();
    }
    if (d == 0) q[g] = red[0];
}

// ---------------------------------------------------------------------------
// fold2: folded A[n][k] -> bf16 hi/lo (row-major N x K), and c[n]
// ---------------------------------------------------------------------------
__global__ void fold2_kernel(const float* __restrict__ WC,
                             const float* __restrict__ W_self,
                             const float* __restrict__ bWC,
                             const float* __restrict__ bias) {
    const int n = blockIdx.x;
    const int k = threadIdx.x;

    float acc = 0.f;
    if (k < 128) {
#pragma unroll 8
        for (int e = 0; e < 128; e++)
            acc += WC[n * 384 + e] * W_self[e * 128 + k];
    } else if (k < 256) {
        const int kk = k - 128;
#pragma unroll 8
        for (int g = 0; g < 128; g++)
            acc += WC[n * 384 + 128 + g] * g_Padj[g * 128 + kk];
    } else {
        const int kk = k - 256;
#pragma unroll 8
        for (int g = 0; g < 128; g++)
            acc += WC[n * 384 + 256 + g] * g_Pdis[g * 128 + kk];
    }
    __nv_bfloat16 h, l;
    split_bf16(acc, h, l);
    g_Bhi[n * 384 + k] = h;
    g_Blo[n * 384 + k] = l;

    float cp = 0.f;
    if (k >= 128 && k < 256) cp = WC[n * 384 + k] * g_qadj[k - 128];
    else if (k >= 256)       cp = WC[n * 384 + k] * g_qdis[k - 256];

    __shared__ float red[384];
    red[k] = cp;
    __syncthreads();
    if (k < 128) red[k] = red[k] + red[k + 128] + red[k + 256];
    __syncthreads();
#pragma unroll
    for (int s = 64; s > 0; s >>= 1) {
        if (k < s) red[k] += red[k + s];
        __syncthreads();
    }
    if (k == 0) g_c[n] = red[0] + bWC[n] + bias[n];
}

// ---------------------------------------------------------------------------
// gather_mean: X[u] = [self | mean_adj | mean_dis] -> bf16 hi/lo
// 16384 CTAs x 128 threads: max outstanding-load parallelism (DRAM-bound).
// ---------------------------------------------------------------------------
__global__ void gather_mean_kernel(const float* __restrict__ emb,
                                   const int* __restrict__ uid,
                                   const int* __restrict__ adj,
                                   const int* __restrict__ dis) {
    const int u = blockIdx.x;
    const int t = threadIdx.x;

    __shared__ int sa[K_NEIGH];
    __shared__ int sd[K_NEIGH];
    __shared__ int sself;
    if (t < 32)       sa[t]      = adj[u * K_NEIGH + t];
    else if (t < 64)  sd[t - 32] = dis[u * K_NEIGH + (t - 32)];
    else if (t == 64) sself      = uid[u];
    __syncthreads();

    float acc_a = 0.f, acc_d = 0.f;
#pragma unroll
    for (int k = 0; k < K_NEIGH; k++) {
        acc_a += emb[(size_t)sa[k] * D_IN + t];
        acc_d += emb[(size_t)sd[k] * D_IN + t];
    }
    const float selfv = emb[(size_t)sself * D_IN + t];
    acc_a *= (1.0f / 32.0f);
    acc_d *= (1.0f / 32.0f);

    const size_t r = (size_t)u * 384;
    __nv_bfloat16 h, l;
    split_bf16(selfv, h, l);  g_Xhi[r + t] = h;        g_Xlo[r + t] = l;
    split_bf16(acc_a, h, l);  g_Xhi[r + 128 + t] = h;  g_Xlo[r + 128 + t] = l;
    split_bf16(acc_d, h, l);  g_Xhi[r + 256 + t] = h;  g_Xlo[r + 256 + t] = l;
}

// ---------------------------------------------------------------------------
// GEMM: Y = leaky( X[16384,384] @ A^T + c ) via mma.sync bf16x3
// Virtual K' = 1152. CTA 128x128, 8 warps (4m x 2n), warp tile 32x64.
// k-chunk 64, 3-stage cp.async pipeline, ONE __syncthreads per iter, 18 iters.
// smem rows padded to 144 B (stride 36 words -> conflict-free ldmatrix).
// ---------------------------------------------------------------------------
#define KCH      64
#define ROWB     144                    // bytes per smem row (64 bf16 + pad)
#define STG_OP   (128 * ROWB)           // 18432 B per operand per stage
#define STG_B    (2 * STG_OP)           // 36864 B per stage (A+B)
#define NSTG     3
#define GSM_TOT  (NSTG * STG_B)         // 110592 B

__global__ __launch_bounds__(256, 2) void gemm_hmma_kernel() {
    extern __shared__ char gsm[];
    const uint32_t base = smem_u32(gsm);

    const int t = threadIdx.x;
    const int lane = t & 31;
    const int wid = t >> 5;
    const int wm = wid & 3;          // 4 m-warps x 32 rows
    const int wn = wid >> 2;         // 2 n-warps x 64 cols
    const int n0 = blockIdx.x * 128;
    const int m0 = blockIdx.y * 128;

    // ldmatrix per-lane address offsets (bytes)
    const uint32_t a_lm = (uint32_t)((lane & 15) * ROWB + (lane >> 4) * 16);
    const uint32_t b_lm = (uint32_t)(((lane & 7) + ((lane >> 4) << 3)) * ROWB
                                     + (((lane >> 3) & 1) << 4));

    float acc[2][8][4];
#pragma unroll
    for (int i = 0; i < 2; i++)
#pragma unroll
        for (int j = 0; j < 8; j++)
#pragma unroll
            for (int q = 0; q < 4; q++) acc[i][j][q] = 0.f;

    // load k-chunk for virtual iter it (0..17) into stage s
    auto load_iter = [&](int it, int s) {
        const int p  = it / 6;                 // product index 0,1,2
        const int kc = (it % 6) * KCH;         // k offset within 384
        const __nv_bfloat16* Asrc = (p < 2) ? g_Xhi : g_Xlo;
        const __nv_bfloat16* Bsrc = (p == 1) ? g_Blo : g_Bhi;
        const uint32_t sb = base + (uint32_t)(s * STG_B);
#pragma unroll
        for (int j = 0; j < 4; j++) {
            const int q = t + j * 256;          // 0..1023
            const int r = q >> 3;               // row 0..127
            const int ch = q & 7;               // 16B chunk (8 per 128B row)
            cp_async16(sb + (uint32_t)(r * ROWB + ch * 16),
                       Asrc + (size_t)(m0 + r) * 384 + kc + ch * 8);
            cp_async16(sb + (uint32_t)(STG_OP + r * ROWB + ch * 16),
                       Bsrc + (size_t)(n0 + r) * 384 + kc + ch * 8);
        }
        cp_commit();
    };

    load_iter(0, 0);
    load_iter(1, 1);

    for (int it = 0; it < 18; it++) {
        if (it == 17) cp_wait<0>(); else cp_wait<1>();
        __syncthreads();

        const int s = it % NSTG;
        const uint32_t a_tile = base + (uint32_t)(s * STG_B + wm * 32 * ROWB) + a_lm;
        const uint32_t b_tile = base + (uint32_t)(s * STG_B + STG_OP + wn * 64 * ROWB) + b_lm;

#pragma unroll
        for (int ks = 0; ks < 4; ks++) {
            uint32_t af[2][4];
            uint32_t bf_[4][4];
#pragma unroll
            for (int mi = 0; mi < 2; mi++)
                ldsm_x4(af[mi][0], af[mi][1], af[mi][2], af[mi][3],
                        a_tile + (uint32_t)(mi * 16 * ROWB + ks * 32));
#pragma unroll
            for (int bj = 0; bj < 4; bj++)
                ldsm_x4(bf_[bj][0], bf_[bj][1], bf_[bj][2], bf_[bj][3],
                        b_tile + (uint32_t)(bj * 16 * ROWB + ks * 32));
#pragma unroll
            for (int mi = 0; mi < 2; mi++)
#pragma unroll
                for (int nj = 0; nj < 8; nj++)
                    mma16816(acc[mi][nj][0], acc[mi][nj][1],
                             acc[mi][nj][2], acc[mi][nj][3],
                             af[mi][0], af[mi][1], af[mi][2], af[mi][3],
                             bf_[nj >> 1][(nj & 1) * 2],
                             bf_[nj >> 1][(nj & 1) * 2 + 1]);
        }

        if (it + 2 < 18) load_iter(it + 2, (it + 2) % NSTG);
    }

    // ---- epilogue: += c, leaky relu, store to g_Y ----
    float cv[8][2];
#pragma unroll
    for (int nj = 0; nj < 8; nj++) {
        const int col = n0 + wn * 64 + nj * 8 + (lane & 3) * 2;
        cv[nj][0] = g_c[col];
        cv[nj][1] = g_c[col + 1];
    }
#pragma unroll
    for (int mi = 0; mi < 2; mi++) {
        const int row = m0 + wm * 32 + mi * 16 + (lane >> 2);
#pragma unroll
        for (int nj = 0; nj < 8; nj++) {
            const int col = n0 + wn * 64 + nj * 8 + (lane & 3) * 2;
            float y0 = acc[mi][nj][0] + cv[nj][0];
            float y1 = acc[mi][nj][1] + cv[nj][1];
            float y2 = acc[mi][nj][2] + cv[nj][0];
            float y3 = acc[mi][nj][3] + cv[nj][1];
            y0 = (y0 > 0.f) ? y0 : 0.2f * y0;
            y1 = (y1 > 0.f) ? y1 : 0.2f * y1;
            y2 = (y2 > 0.f) ? y2 : 0.2f * y2;
            y3 = (y3 > 0.f) ? y3 : 0.2f * y3;
            *(float2*)&g_Y[(size_t)row * 384 + col]       = make_float2(y0, y1);
            *(float2*)&g_Y[(size_t)(row + 8) * 384 + col] = make_float2(y2, y3);
        }
    }
}

// ---------------------------------------------------------------------------
// norm_gather: out[b] = normalize(Y[nodes_idx[b]])
// ---------------------------------------------------------------------------
__global__ void norm_gather_kernel(const int* __restrict__ nodes_idx,
                                   float* __restrict__ out) {
    const int w = threadIdx.x >> 5;
    const int l = threadIdx.x & 31;
    const int b = blockIdx.x * 8 + w;
    const int u = nodes_idx[b];

    const float4* yr = (const float4*)(g_Y + (size_t)u * 384);
    float4 v0 = yr[l];
    float4 v1 = yr[l + 32];
    float4 v2 = yr[l + 64];

    float s = v0.x * v0.x + v0.y * v0.y + v0.z * v0.z + v0.w * v0.w
            + v1.x * v1.x + v1.y * v1.y + v1.z * v1.z + v1.w * v1.w
            + v2.x * v2.x + v2.y * v2.y + v2.z * v2.z + v2.w * v2.w;
#pragma unroll
    for (int off = 16; off > 0; off >>= 1)
        s += __shfl_xor_sync(0xffffffffu, s, off);

    const float inv = 1.0f / fmaxf(sqrtf(s), 1e-12f);

    float4* o = (float4*)(out + (size_t)b * 384);
    v0.x *= inv; v0.y *= inv; v0.z *= inv; v0.w *= inv;
    v1.x *= inv; v1.y *= inv; v1.z *= inv; v1.w *= inv;
    v2.x *= inv; v2.y *= inv; v2.z *= inv; v2.w *= inv;
    o[l]      = v0;
    o[l + 32] = v1;
    o[l + 64] = v2;
}

// ---------------------------------------------------------------------------
extern "C" void kernel_launch(void* const* d_in, const int* in_sizes, int n_in,
                              void* d_out, int out_size) {
    const float* emb    = (const float*)d_in[0];
    const float* Wa_adj = (const float*)d_in[1];
    const float* ba_adj = (const float*)d_in[2];
    const float* Wa_dis = (const float*)d_in[3];
    const float* ba_dis = (const float*)d_in[4];
    const float* W_self = (const float*)d_in[5];
    const float* W_adj  = (const float*)d_in[6];
    const float* W_dis  = (const float*)d_in[7];
    const float* WC     = (const float*)d_in[8];
    const float* bWC    = (const float*)d_in[9];
    const float* bias   = (const float*)d_in[10];
    const int* uid      = (const int*)d_in[11];
    const int* adj      = (const int*)d_in[12];
    const int* dis      = (const int*)d_in[13];
    const int* nidx     = (const int*)d_in[14];
    float* out          = (float*)d_out;

    cudaFuncSetAttribute(gemm_hmma_kernel,
                         cudaFuncAttributeMaxDynamicSharedMemorySize, GSM_TOT);

    fold1_kernel<<<dim3(128, 2), 128>>>(W_adj, Wa_adj, ba_adj,
                                        W_dis, Wa_dis, ba_dis);
    fold2_kernel<<<384, 384>>>(WC, W_self, bWC, bias);
    gather_mean_kernel<<<U_NODES, 128>>>(emb, uid, adj, dis);
    gemm_hmma_kernel<<<dim3(3, 128), 256, GSM_TOT>>>();
    norm_gather_kernel<<<B_OUT / 8, 256>>>(nidx, out);
}

// round 7
// speedup vs baseline: 1.6598x; 1.2244x over previous
#include <cuda_runtime.h>
#include <cuda_bf16.h>
#include <cuda_fp16.h>
#include <cstdint>
#include <cstddef>

// ---------------------------------------------------------------------------
// SageLayer pipeline v6: single-product fp16 HMMA GEMM (K=384).
//   out[b] = normalize(leaky( X @ A^T + c ))[nodes_idx]
//   X[u] = [ emb[uid[u]] | mean_k emb[adj[u,k]] | mean_k emb[dis[u,k]] ]
//   A, c folded (exact fp32 algebra). X, A rounded to fp16 -> rel_err ~2e-4,
//   5x under the 1e-3 threshold (error model validated in rounds 3-5).
// ---------------------------------------------------------------------------

#define U_NODES 16384
#define K_NEIGH 32
#define D_IN    128
#define D_OUT   384
#define B_OUT   32768

// ---- device scratch ----
__device__ __align__(16) float g_Padj[128 * 128];
__device__ __align__(16) float g_Pdis[128 * 128];
__device__ __align__(16) float g_qadj[128];
__device__ __align__(16) float g_qdis[128];
__device__ __align__(16) float g_c[384];
__device__ __align__(16) __half g_X[(size_t)U_NODES * 384];
__device__ __align__(16) __half g_B[384 * 384];            // folded A[n][k]
__device__ __align__(16) float g_Y[(size_t)U_NODES * 384];

// ---- helpers ----
__device__ __forceinline__ uint32_t smem_u32(const void* p) {
    uint32_t a;
    asm("{ .reg .u64 t; cvta.to.shared.u64 t, %1; cvt.u32.u64 %0, t; }"
        : "=r"(a) : "l"(p));
    return a;
}
__device__ __forceinline__ void cp_async16(uint32_t dst, const void* src) {
    asm volatile("cp.async.cg.shared.global [%0], [%1], 16;"
                 :: "r"(dst), "l"(src) : "memory");
}
__device__ __forceinline__ void cp_commit() {
    asm volatile("cp.async.commit_group;" ::: "memory");
}
template <int N>
__device__ __forceinline__ void cp_wait() {
    asm volatile("cp.async.wait_group %0;" :: "n"(N) : "memory");
}
__device__ __forceinline__ void ldsm_x4(uint32_t& r0, uint32_t& r1,
                                        uint32_t& r2, uint32_t& r3, uint32_t a) {
    asm volatile("ldmatrix.sync.aligned.m8n8.x4.shared.b16 {%0,%1,%2,%3}, [%4];"
                 : "=r"(r0), "=r"(r1), "=r"(r2), "=r"(r3) : "r"(a));
}
__device__ __forceinline__ void mma16816(float& c0, float& c1, float& c2, float& c3,
                                         uint32_t a0, uint32_t a1, uint32_t a2, uint32_t a3,
                                         uint32_t b0, uint32_t b1) {
    asm volatile(
        "mma.sync.aligned.m16n8k16.row.col.f32.f16.f16.f32 "
        "{%0,%1,%2,%3}, {%4,%5,%6,%7}, {%8,%9}, {%0,%1,%2,%3};"
        : "+f"(c0), "+f"(c1), "+f"(c2), "+f"(c3)
        : "r"(a0), "r"(a1), "r"(a2), "r"(a3), "r"(b0), "r"(b1));
}

// ---------------------------------------------------------------------------
// fold1: P = W @ Wa (128x128), q = W @ ba   for adj/dis
// ---------------------------------------------------------------------------
__global__ void fold1_kernel(const float* __restrict__ W_adj,
                             const float* __restrict__ Wa_adj,
                             const float* __restrict__ ba_adj,
                             const float* __restrict__ W_dis,
                             const float* __restrict__ Wa_dis,
                             const float* __restrict__ ba_dis) {
    const int g = blockIdx.x;
    const int which = blockIdx.y;
    const int d = threadIdx.x;

    const float* W  = which ? W_dis  : W_adj;
    const float* Wa = which ? Wa_dis : Wa_adj;
    const float* ba = which ? ba_dis : ba_adj;
    float* P = which ? g_Pdis : g_Padj;
    float* q = which ? g_qdis : g_qadj;

    float acc = 0.f;
#pragma unroll 8
    for (int e = 0; e < 128; e++)
        acc += W[g * 128 + e] * Wa[e * 128 + d];
    P[g * 128 + d] = acc;

    __shared__ float red[128];
    red[d] = W[g * 128 + d] * ba[d];
    __syncthreads();
#pragma unroll
    for (int s = 64; s > 0; s >>= 1) {
        if (d < s) red[d] += red[d + s];
        __syncthreads();
    }
    if (d == 0) q[g] = red[0];
}

// ---------------------------------------------------------------------------
// fold2: folded A[n][k] -> fp16 (row-major N x K), and c[n]
// ---------------------------------------------------------------------------
__global__ void fold2_kernel(const float* __restrict__ WC,
                             const float* __restrict__ W_self,
                             const float* __restrict__ bWC,
                             const float* __restrict__ bias) {
    const int n = blockIdx.x;
    const int k = threadIdx.x;

    float acc = 0.f;
    if (k < 128) {
#pragma unroll 8
        for (int e = 0; e < 128; e++)
            acc += WC[n * 384 + e] * W_self[e * 128 + k];
    } else if (k < 256) {
        const int kk = k - 128;
#pragma unroll 8
        for (int g = 0; g < 128; g++)
            acc += WC[n * 384 + 128 + g] * g_Padj[g * 128 + kk];
    } else {
        const int kk = k - 256;
#pragma unroll 8
        for (int g = 0; g < 128; g++)
            acc += WC[n * 384 + 256 + g] * g_Pdis[g * 128 + kk];
    }
    g_B[n * 384 + k] = __float2half_rn(acc);

    float cp = 0.f;
    if (k >= 128 && k < 256) cp = WC[n * 384 + k] * g_qadj[k - 128];
    else if (k >= 256)       cp = WC[n * 384 + k] * g_qdis[k - 256];

    __shared__ float red[384];
    red[k] = cp;
    __syncthreads();
    if (k < 128) red[k] = red[k] + red[k + 128] + red[k + 256];
    __syncthreads();
#pragma unroll
    for (int s = 64; s > 0; s >>= 1) {
        if (k < s) red[k] += red[k + s];
        __syncthreads();
    }
    if (k == 0) g_c[n] = red[0] + bWC[n] + bias[n];
}

// ---------------------------------------------------------------------------
// gather_mean: X[u] = [self | mean_adj | mean_dis] -> fp16
// 16384 CTAs x 128 threads: max outstanding-load parallelism (DRAM-bound).
// ---------------------------------------------------------------------------
__global__ void gather_mean_kernel(const float* __restrict__ emb,
                                   const int* __restrict__ uid,
                                   const int* __restrict__ adj,
                                   const int* __restrict__ dis) {
    const int u = blockIdx.x;
    const int t = threadIdx.x;

    __shared__ int sa[K_NEIGH];
    __shared__ int sd[K_NEIGH];
    __shared__ int sself;
    if (t < 32)       sa[t]      = adj[u * K_NEIGH + t];
    else if (t < 64)  sd[t - 32] = dis[u * K_NEIGH + (t - 32)];
    else if (t == 64) sself      = uid[u];
    __syncthreads();

    float acc_a = 0.f, acc_d = 0.f;
#pragma unroll
    for (int k = 0; k < K_NEIGH; k++) {
        acc_a += emb[(size_t)sa[k] * D_IN + t];
        acc_d += emb[(size_t)sd[k] * D_IN + t];
    }
    const float selfv = emb[(size_t)sself * D_IN + t];

    const size_t r = (size_t)u * 384;
    g_X[r + t]       = __float2half_rn(selfv);
    g_X[r + 128 + t] = __float2half_rn(acc_a * (1.0f / 32.0f));
    g_X[r + 256 + t] = __float2half_rn(acc_d * (1.0f / 32.0f));
}

// ---------------------------------------------------------------------------
// GEMM: Y = leaky( X[16384,384] @ A^T + c ) via single-product fp16 mma.sync
// K = 384, k-chunk 64, 6 iters. CTA 128x128, 8 warps (4m x 2n), warp 32x64.
// 3-stage cp.async pipeline, ONE __syncthreads per iter.
// smem rows padded to 144 B (stride 36 words -> conflict-free ldmatrix).
// ---------------------------------------------------------------------------
#define KCH      64
#define ROWB     144                    // bytes per smem row (64 fp16 + pad)
#define STG_OP   (128 * ROWB)           // 18432 B per operand per stage
#define STG_B    (2 * STG_OP)           // 36864 B per stage (A+B)
#define NSTG     3
#define GSM_TOT  (NSTG * STG_B)         // 110592 B

__global__ __launch_bounds__(256, 2) void gemm_hmma_kernel() {
    extern __shared__ char gsm[];
    const uint32_t base = smem_u32(gsm);

    const int t = threadIdx.x;
    const int lane = t & 31;
    const int wid = t >> 5;
    const int wm = wid & 3;          // 4 m-warps x 32 rows
    const int wn = wid >> 2;         // 2 n-warps x 64 cols
    const int n0 = blockIdx.x * 128;
    const int m0 = blockIdx.y * 128;

    // ldmatrix per-lane address offsets (bytes)
    const uint32_t a_lm = (uint32_t)((lane & 15) * ROWB + (lane >> 4) * 16);
    const uint32_t b_lm = (uint32_t)(((lane & 7) + ((lane >> 4) << 3)) * ROWB
                                     + (((lane >> 3) & 1) << 4));

    float acc[2][8][4];
#pragma unroll
    for (int i = 0; i < 2; i++)
#pragma unroll
        for (int j = 0; j < 8; j++)
#pragma unroll
            for (int q = 0; q < 4; q++) acc[i][j][q] = 0.f;

    // load k-chunk for iter it (0..5) into stage s
    auto load_iter = [&](int it, int s) {
        const int kc = it * KCH;
        const uint32_t sb = base + (uint32_t)(s * STG_B);
#pragma unroll
        for (int j = 0; j < 4; j++) {
            const int q = t + j * 256;          // 0..1023
            const int r = q >> 3;               // row 0..127
            const int ch = q & 7;               // 16B chunk (8 per 128B row)
            cp_async16(sb + (uint32_t)(r * ROWB + ch * 16),
                       g_X + (size_t)(m0 + r) * 384 + kc + ch * 8);
            cp_async16(sb + (uint32_t)(STG_OP + r * ROWB + ch * 16),
                       g_B + (size_t)(n0 + r) * 384 + kc + ch * 8);
        }
        cp_commit();
    };

    load_iter(0, 0);
    load_iter(1, 1);

    for (int it = 0; it < 6; it++) {
        if (it == 5) cp_wait<0>(); else cp_wait<1>();
        __syncthreads();

        const int s = it % NSTG;
        const uint32_t a_tile = base + (uint32_t)(s * STG_B + wm * 32 * ROWB) + a_lm;
        const uint32_t b_tile = base + (uint32_t)(s * STG_B + STG_OP + wn * 64 * ROWB) + b_lm;

#pragma unroll
        for (int ks = 0; ks < 4; ks++) {
            uint32_t af[2][4];
            uint32_t bf_[4][4];
#pragma unroll
            for (int mi = 0; mi < 2; mi++)
                ldsm_x4(af[mi][0], af[mi][1], af[mi][2], af[mi][3],
                        a_tile + (uint32_t)(mi * 16 * ROWB + ks * 32));
#pragma unroll
            for (int bj = 0; bj < 4; bj++)
                ldsm_x4(bf_[bj][0], bf_[bj][1], bf_[bj][2], bf_[bj][3],
                        b_tile + (uint32_t)(bj * 16 * ROWB + ks * 32));
#pragma unroll
            for (int mi = 0; mi < 2; mi++)
#pragma unroll
                for (int nj = 0; nj < 8; nj++)
                    mma16816(acc[mi][nj][0], acc[mi][nj][1],
                             acc[mi][nj][2], acc[mi][nj][3],
                             af[mi][0], af[mi][1], af[mi][2], af[mi][3],
                             bf_[nj >> 1][(nj & 1) * 2],
                             bf_[nj >> 1][(nj & 1) * 2 + 1]);
        }

        if (it + 2 < 6) load_iter(it + 2, (it + 2) % NSTG);
    }

    // ---- epilogue: += c, leaky relu, store to g_Y ----
    float cv[8][2];
#pragma unroll
    for (int nj = 0; nj < 8; nj++) {
        const int col = n0 + wn * 64 + nj * 8 + (lane & 3) * 2;
        cv[nj][0] = g_c[col];
        cv[nj][1] = g_c[col + 1];
    }
#pragma unroll
    for (int mi = 0; mi < 2; mi++) {
        const int row = m0 + wm * 32 + mi * 16 + (lane >> 2);
#pragma unroll
        for (int nj = 0; nj < 8; nj++) {
            const int col = n0 + wn * 64 + nj * 8 + (lane & 3) * 2;
            float y0 = acc[mi][nj][0] + cv[nj][0];
            float y1 = acc[mi][nj][1] + cv[nj][1];
            float y2 = acc[mi][nj][2] + cv[nj][0];
            float y3 = acc[mi][nj][3] + cv[nj][1];
            y0 = (y0 > 0.f) ? y0 : 0.2f * y0;
            y1 = (y1 > 0.f) ? y1 : 0.2f * y1;
            y2 = (y2 > 0.f) ? y2 : 0.2f * y2;
            y3 = (y3 > 0.f) ? y3 : 0.2f * y3;
            *(float2*)&g_Y[(size_t)row * 384 + col]       = make_float2(y0, y1);
            *(float2*)&g_Y[(size_t)(row + 8) * 384 + col] = make_float2(y2, y3);
        }
    }
}

// ---------------------------------------------------------------------------
// norm_gather: out[b] = normalize(Y[nodes_idx[b]])
// ---------------------------------------------------------------------------
__global__ void norm_gather_kernel(const int* __restrict__ nodes_idx,
                                   float* __restrict__ out) {
    const int w = threadIdx.x >> 5;
    const int l = threadIdx.x & 31;
    const int b = blockIdx.x * 8 + w;
    const int u = nodes_idx[b];

    const float4* yr = (const float4*)(g_Y + (size_t)u * 384);
    float4 v0 = yr[l];
    float4 v1 = yr[l + 32];
    float4 v2 = yr[l + 64];

    float s = v0.x * v0.x + v0.y * v0.y + v0.z * v0.z + v0.w * v0.w
            + v1.x * v1.x + v1.y * v1.y + v1.z * v1.z + v1.w * v1.w
            + v2.x * v2.x + v2.y * v2.y + v2.z * v2.z + v2.w * v2.w;
#pragma unroll
    for (int off = 16; off > 0; off >>= 1)
        s += __shfl_xor_sync(0xffffffffu, s, off);

    const float inv = 1.0f / fmaxf(sqrtf(s), 1e-12f);

    float4* o = (float4*)(out + (size_t)b * 384);
    v0.x *= inv; v0.y *= inv; v0.z *= inv; v0.w *= inv;
    v1.x *= inv; v1.y *= inv; v1.z *= inv; v1.w *= inv;
    v2.x *= inv; v2.y *= inv; v2.z *= inv; v2.w *= inv;
    o[l]      = v0;
    o[l + 32] = v1;
    o[l + 64] = v2;
}

// ---------------------------------------------------------------------------
extern "C" void kernel_launch(void* const* d_in, const int* in_sizes, int n_in,
                              void* d_out, int out_size) {
    const float* emb    = (const float*)d_in[0];
    const float* Wa_adj = (const float*)d_in[1];
    const float* ba_adj = (const float*)d_in[2];
    const float* Wa_dis = (const float*)d_in[3];
    const float* ba_dis = (const float*)d_in[4];
    const float* W_self = (const float*)d_in[5];
    const float* W_adj  = (const float*)d_in[6];
    const float* W_dis  = (const float*)d_in[7];
    const float* WC     = (const float*)d_in[8];
    const float* bWC    = (const float*)d_in[9];
    const float* bias   = (const float*)d_in[10];
    const int* uid      = (const int*)d_in[11];
    const int* adj      = (const int*)d_in[12];
    const int* dis      = (const int*)d_in[13];
    const int* nidx     = (const int*)d_in[14];
    float* out          = (float*)d_out;

    cudaFuncSetAttribute(gemm_hmma_kernel,
                         cudaFuncAttributeMaxDynamicSharedMemorySize, GSM_TOT);

    fold1_kernel<<<dim3(128, 2), 128>>>(W_adj, Wa_adj, ba_adj,
                                        W_dis, Wa_dis, ba_dis);
    fold2_kernel<<<384, 384>>>(WC, W_self, bWC, bias);
    gather_mean_kernel<<<U_NODES, 128>>>(emb, uid, adj, dis);
    gemm_hmma_kernel<<<dim3(3, 128), 256, GSM_TOT>>>();
    norm_gather_kernel<<<B_OUT / 8, 256>>>(nidx, out);
}